// round 6
// baseline (speedup 1.0000x reference)
#include <cuda_runtime.h>
#include <cstdint>

#define BDIM 8192
#define KTOP 3
#define MARGIN 0.8f
#define NEG_FILL -50.0f

#define THREADS 256
#define NWARP (THREADS / 32)
#define VPT 8                      // float4 per thread per row
#define GRID 592                   // 148 SMs * 4 persistent CTAs

__device__ float g_row_partial[BDIM];
__device__ unsigned int g_ctr = 0;

// Merge sorted-descending triple (b0,b1,b2) into (t0,t1,t2). 7 FMNMX, branchless.
__device__ __forceinline__ void merge3(float& t0, float& t1, float& t2,
                                       float b0, float b1, float b2) {
    const float u = fminf(t0, b0);
    const float q = fmaxf(t1, b1);
    const float z = fminf(u, q);
    t0 = fmaxf(t0, b0);
    t1 = fmaxf(u, q);
    t2 = fmaxf(fmaxf(z, t2), b2);
}

// Sorted-descending top-3 of a float4. 9 FMNMX, branchless.
__device__ __forceinline__ void sort4_top3(float4 v, float& s0, float& s1, float& s2) {
    const float m01 = fmaxf(v.x, v.y), n01 = fminf(v.x, v.y);
    const float m23 = fmaxf(v.z, v.w), n23 = fminf(v.z, v.w);
    const float b = fminf(m01, m23);
    const float c = fmaxf(n01, n23);
    s0 = fmaxf(m01, m23);
    s1 = fmaxf(b, c);
    s2 = fminf(b, c);
}

__device__ __forceinline__ void load_row(float4* __restrict__ buf,
                                         const float* __restrict__ inp,
                                         int row, int t) {
    const float4* __restrict__ rp =
        reinterpret_cast<const float4*>(inp + (size_t)row * BDIM);
    #pragma unroll
    for (int i = 0; i < VPT; i++)
        buf[i] = rp[t + i * THREADS];
}

struct Smem {
    float sm[NWARP][3];
    float sp;          // original diagonal value of the row in flight
    int   last;
};

__device__ __forceinline__ void process_row(float4* __restrict__ buf,
                                            int row, int t, Smem* s) {
    // ---- mask the diagonal; its owner stashes sim_p into smem ----
    const int diag4 = row >> 2;
    if (t == (diag4 & (THREADS - 1))) {          // cold: one warp diverges
        const int slot = diag4 >> 8;
        const int dl = row & 3;
        #pragma unroll
        for (int i = 0; i < VPT; i++) {
            if (i == slot) {
                float* e = reinterpret_cast<float*>(&buf[i]);
                s->sp = e[dl];
                e[dl] = -1e30f;
            }
        }
    }

    // ---- branchless top-3 scan: 16 FMNMX per float4 ----
    float t0, t1, t2;
    sort4_top3(buf[0], t0, t1, t2);
    #pragma unroll
    for (int i = 1; i < VPT; i++) {
        float s0, s1, s2;
        sort4_top3(buf[i], s0, s1, s2);
        merge3(t0, t1, t2, s0, s1, s2);
    }

    // ---- warp merge ----
    #pragma unroll
    for (int off = 16; off > 0; off >>= 1) {
        const float a0 = __shfl_down_sync(0xFFFFFFFFu, t0, off);
        const float a1 = __shfl_down_sync(0xFFFFFFFFu, t1, off);
        const float a2 = __shfl_down_sync(0xFFFFFFFFu, t2, off);
        merge3(t0, t1, t2, a0, a1, a2);
    }

    const int wid = t >> 5;
    const int lid = t & 31;
    if (lid == 0) { s->sm[wid][0] = t0; s->sm[wid][1] = t1; s->sm[wid][2] = t2; }
    __syncthreads();

    if (t == 0) {
        #pragma unroll
        for (int w = 1; w < NWARP; w++)
            merge3(t0, t1, t2, s->sm[w][0], s->sm[w][1], s->sm[w][2]);

        // ---- epilogue: hinge + softmax re-weighting (K=3, tau=0.1) ----
        const float sp = s->sp;

        const float l0 = fmaxf(t0 - sp + MARGIN, 0.0f);
        const float l1 = fmaxf(t1 - sp + MARGIN, 0.0f);
        const float l2 = fmaxf(t2 - sp + MARGIN, 0.0f);

        const float m0 = (l0 == 0.0f) ? NEG_FILL : t0;
        const float m1 = (l1 == 0.0f) ? NEG_FILL : t1;
        const float m2 = (l2 == 0.0f) ? NEG_FILL : t2;

        const float mm = fmaxf(m0, fmaxf(m1, m2));
        const float e0 = __expf((m0 - mm) * 10.0f);   // /tau = *10
        const float e1 = __expf((m1 - mm) * 10.0f);
        const float e2 = __expf((m2 - mm) * 10.0f);
        const float sum = e0 + e1 + e2;

        g_row_partial[row] = (l0 * e0 + l1 * e1 + l2 * e2) / sum;
    }
    __syncthreads();   // protect s->sp / s->sm reuse next row
}

__global__ __launch_bounds__(THREADS)
void fused_topk_loss_kernel(const float* __restrict__ inp, float* __restrict__ out) {
    __shared__ Smem s;

    const int t = threadIdx.x;
    const int row0 = blockIdx.x;

    float4 bufA[VPT], bufB[VPT];

    // prime the pipeline
    load_row(bufA, inp, row0, t);

    // ping-pong: prefetch row r+GRID while processing row r
    for (int r = row0; r < BDIM; r += 2 * GRID) {
        const int r1 = r + GRID;
        const int r2 = r + 2 * GRID;
        if (r1 < BDIM) load_row(bufB, inp, r1, t);
        process_row(bufA, r, t, &s);
        if (r2 < BDIM) load_row(bufA, inp, r2, t);
        if (r1 < BDIM) process_row(bufB, r1, t, &s);
    }

    // ---- CTA completion: last CTA does the final mean reduction ----
    if (t == 0) {
        __threadfence();
        const unsigned c = atomicAdd(&g_ctr, 1u);
        s.last = (c == (unsigned)(GRID - 1)) ? 1 : 0;
    }
    __syncthreads();

    if (s.last) {
        float acc = 0.0f;
        #pragma unroll
        for (int i = 0; i < BDIM / THREADS; i++)
            acc += __ldcg(&g_row_partial[t + i * THREADS]);

        #pragma unroll
        for (int off = 16; off > 0; off >>= 1)
            acc += __shfl_down_sync(0xFFFFFFFFu, acc, off);

        __shared__ float rsm[NWARP];
        const int wid = t >> 5;
        const int lid = t & 31;
        if (lid == 0) rsm[wid] = acc;
        __syncthreads();

        if (t == 0) {
            float ssum = 0.0f;
            #pragma unroll
            for (int w = 0; w < NWARP; w++) ssum += rsm[w];
            out[0] = ssum / (float)(BDIM * KTOP);
            g_ctr = 0;   // reset for next graph replay (deterministic)
        }
    }
}

extern "C" void kernel_launch(void* const* d_in, const int* in_sizes, int n_in,
                              void* d_out, int out_size) {
    const float* inp = (const float*)d_in[0];
    // d_in[1] is target == eye(B); masking reduces to diagonal exclusion, so unused.
    float* out = (float*)d_out;

    fused_topk_loss_kernel<<<GRID, THREADS>>>(inp, out);
}

// round 7
// speedup vs baseline: 1.2589x; 1.2589x over previous
#include <cuda_runtime.h>
#include <cstdint>

#define BDIM 8192
#define KTOP 3
#define MARGIN 0.8f
#define NEG_FILL -50.0f

#define THREADS 512
#define NWARP (THREADS / 32)       // 16
#define VPT 4                      // float4 per thread PER ROW (2 rows -> 8 LDGs)
#define GRID (BDIM / 2)            // 4096 CTAs, 2 rows each

__device__ float g_row_partial[BDIM];
__device__ unsigned int g_ctr = 0;

// Merge sorted-descending triple (b0,b1,b2) into (t0,t1,t2). 7 FMNMX, branchless.
__device__ __forceinline__ void merge3(float& t0, float& t1, float& t2,
                                       float b0, float b1, float b2) {
    const float u = fminf(t0, b0);
    const float q = fmaxf(t1, b1);
    const float z = fminf(u, q);
    t0 = fmaxf(t0, b0);
    t1 = fmaxf(u, q);
    t2 = fmaxf(fmaxf(z, t2), b2);
}

// Sorted-descending top-3 of a float4. 9 FMNMX, branchless.
__device__ __forceinline__ void sort4_top3(float4 v, float& s0, float& s1, float& s2) {
    const float m01 = fmaxf(v.x, v.y), n01 = fminf(v.x, v.y);
    const float m23 = fmaxf(v.z, v.w), n23 = fminf(v.z, v.w);
    const float b = fminf(m01, m23);
    const float c = fmaxf(n01, n23);
    s0 = fmaxf(m01, m23);
    s1 = fmaxf(b, c);
    s2 = fminf(b, c);
}

// Mask diagonal element of one row held in buf[VPT]; owner stashes sim_p.
__device__ __forceinline__ void mask_diag(float4* buf, int row, int t, float* sp_slot) {
    const int diag4 = row >> 2;                       // f4 index within the row
    if (t == (diag4 & (THREADS - 1))) {               // cold: one warp diverges
        const int slot = diag4 >> 9;                  // which of VPT=4 f4s
        const int dl = row & 3;
        #pragma unroll
        for (int i = 0; i < VPT; i++) {
            if (i == slot) {
                float* e = reinterpret_cast<float*>(&buf[i]);
                *sp_slot = e[dl];
                e[dl] = -1e30f;
            }
        }
    }
}

// Final CTA-level merge + hinge/softmax epilogue for one row (single thread).
__device__ __forceinline__ void epilogue(const float (*sm)[6], int base,
                                         int row) {
    float t0 = sm[0][base + 0], t1 = sm[0][base + 1], t2 = sm[0][base + 2];
    #pragma unroll
    for (int w = 1; w < NWARP; w++)
        merge3(t0, t1, t2, sm[w][base + 0], sm[w][base + 1], sm[w][base + 2]);

    const float sp = sm[0][base + 3];   // stashed sim_p (see layout below)

    const float l0 = fmaxf(t0 - sp + MARGIN, 0.0f);
    const float l1 = fmaxf(t1 - sp + MARGIN, 0.0f);
    const float l2 = fmaxf(t2 - sp + MARGIN, 0.0f);

    const float m0 = (l0 == 0.0f) ? NEG_FILL : t0;
    const float m1 = (l1 == 0.0f) ? NEG_FILL : t1;
    const float m2 = (l2 == 0.0f) ? NEG_FILL : t2;

    const float mm = fmaxf(m0, fmaxf(m1, m2));
    const float e0 = __expf((m0 - mm) * 10.0f);   // /tau = *10
    const float e1 = __expf((m1 - mm) * 10.0f);
    const float e2 = __expf((m2 - mm) * 10.0f);
    const float s  = e0 + e1 + e2;

    g_row_partial[row] = (l0 * e0 + l1 * e1 + l2 * e2) / s;
}

__global__ __launch_bounds__(THREADS, 2)
void fused_topk_loss_kernel(const float* __restrict__ inp, float* __restrict__ out) {
    // sm[w][0..2] = row-A triple, sm[w][3..5] = row-B triple (per warp).
    // sim_p values are stashed into sm[0][3]-slot trick? No: separate cells:
    __shared__ float sm[NWARP][6];
    __shared__ float s_spA, s_spB;
    __shared__ int s_last;

    const int t = threadIdx.x;
    const int rowA = blockIdx.x * 2;
    const int rowB = rowA + 1;

    const float4* __restrict__ rpA =
        reinterpret_cast<const float4*>(inp + (size_t)rowA * BDIM);
    const float4* __restrict__ rpB =
        reinterpret_cast<const float4*>(inp + (size_t)rowB * BDIM);

    // ---- batch ALL 8 loads (2 rows x 4 f4), streaming policy ----
    float4 a[VPT], b[VPT];
    #pragma unroll
    for (int i = 0; i < VPT; i++) a[i] = __ldcs(&rpA[t + i * THREADS]);
    #pragma unroll
    for (int i = 0; i < VPT; i++) b[i] = __ldcs(&rpB[t + i * THREADS]);

    // ---- mask diagonals (one owner thread per row) ----
    mask_diag(a, rowA, t, &s_spA);
    mask_diag(b, rowB, t, &s_spB);

    // ---- branchless top-3 scans, both rows ----
    float a0, a1, a2, b0, b1, b2;
    sort4_top3(a[0], a0, a1, a2);
    sort4_top3(b[0], b0, b1, b2);
    #pragma unroll
    for (int i = 1; i < VPT; i++) {
        float s0, s1, s2;
        sort4_top3(a[i], s0, s1, s2);
        merge3(a0, a1, a2, s0, s1, s2);
        sort4_top3(b[i], s0, s1, s2);
        merge3(b0, b1, b2, s0, s1, s2);
    }

    // ---- warp merges ----
    #pragma unroll
    for (int off = 16; off > 0; off >>= 1) {
        float x0 = __shfl_down_sync(0xFFFFFFFFu, a0, off);
        float x1 = __shfl_down_sync(0xFFFFFFFFu, a1, off);
        float x2 = __shfl_down_sync(0xFFFFFFFFu, a2, off);
        merge3(a0, a1, a2, x0, x1, x2);
        x0 = __shfl_down_sync(0xFFFFFFFFu, b0, off);
        x1 = __shfl_down_sync(0xFFFFFFFFu, b1, off);
        x2 = __shfl_down_sync(0xFFFFFFFFu, b2, off);
        merge3(b0, b1, b2, x0, x1, x2);
    }

    const int wid = t >> 5;
    const int lid = t & 31;
    if (lid == 0) {
        sm[wid][0] = a0; sm[wid][1] = a1; sm[wid][2] = a2;
        sm[wid][3] = b0; sm[wid][4] = b1; sm[wid][5] = b2;
    }
    __syncthreads();

    // threads 0 and 32 (different warps -> parallel) finish rows A and B
    if (t == 0) {
        float t0 = sm[0][0], t1 = sm[0][1], t2 = sm[0][2];
        #pragma unroll
        for (int w = 1; w < NWARP; w++) merge3(t0, t1, t2, sm[w][0], sm[w][1], sm[w][2]);
        const float sp = s_spA;
        const float l0 = fmaxf(t0 - sp + MARGIN, 0.0f);
        const float l1 = fmaxf(t1 - sp + MARGIN, 0.0f);
        const float l2 = fmaxf(t2 - sp + MARGIN, 0.0f);
        const float m0 = (l0 == 0.0f) ? NEG_FILL : t0;
        const float m1 = (l1 == 0.0f) ? NEG_FILL : t1;
        const float m2 = (l2 == 0.0f) ? NEG_FILL : t2;
        const float mm = fmaxf(m0, fmaxf(m1, m2));
        const float e0 = __expf((m0 - mm) * 10.0f);
        const float e1 = __expf((m1 - mm) * 10.0f);
        const float e2 = __expf((m2 - mm) * 10.0f);
        g_row_partial[rowA] = (l0 * e0 + l1 * e1 + l2 * e2) / (e0 + e1 + e2);
    }
    if (t == 32) {
        float t0 = sm[0][3], t1 = sm[0][4], t2 = sm[0][5];
        #pragma unroll
        for (int w = 1; w < NWARP; w++) merge3(t0, t1, t2, sm[w][3], sm[w][4], sm[w][5]);
        const float sp = s_spB;
        const float l0 = fmaxf(t0 - sp + MARGIN, 0.0f);
        const float l1 = fmaxf(t1 - sp + MARGIN, 0.0f);
        const float l2 = fmaxf(t2 - sp + MARGIN, 0.0f);
        const float m0 = (l0 == 0.0f) ? NEG_FILL : t0;
        const float m1 = (l1 == 0.0f) ? NEG_FILL : t1;
        const float m2 = (l2 == 0.0f) ? NEG_FILL : t2;
        const float mm = fmaxf(m0, fmaxf(m1, m2));
        const float e0 = __expf((m0 - mm) * 10.0f);
        const float e1 = __expf((m1 - mm) * 10.0f);
        const float e2 = __expf((m2 - mm) * 10.0f);
        g_row_partial[rowB] = (l0 * e0 + l1 * e1 + l2 * e2) / (e0 + e1 + e2);
    }
    __syncthreads();

    if (t == 0) {
        __threadfence();
        const unsigned c = atomicAdd(&g_ctr, 1u);
        s_last = (c == (unsigned)(GRID - 1)) ? 1 : 0;
    }
    __syncthreads();

    // ---- last CTA: final mean reduction (no tail kernel) ----
    if (s_last) {
        float acc = 0.0f;
        #pragma unroll
        for (int i = 0; i < BDIM / THREADS; i++)
            acc += __ldcg(&g_row_partial[t + i * THREADS]);

        #pragma unroll
        for (int off = 16; off > 0; off >>= 1)
            acc += __shfl_down_sync(0xFFFFFFFFu, acc, off);

        __shared__ float rsm[NWARP];
        if (lid == 0) rsm[wid] = acc;
        __syncthreads();

        if (t == 0) {
            float ssum = 0.0f;
            #pragma unroll
            for (int w = 0; w < NWARP; w++) ssum += rsm[w];
            out[0] = ssum / (float)(BDIM * KTOP);
            g_ctr = 0;   // reset for next graph replay (deterministic)
        }
    }
}

extern "C" void kernel_launch(void* const* d_in, const int* in_sizes, int n_in,
                              void* d_out, int out_size) {
    const float* inp = (const float*)d_in[0];
    // d_in[1] is target == eye(B); masking reduces to diagonal exclusion, so unused.
    float* out = (float*)d_out;

    fused_topk_loss_kernel<<<GRID, THREADS>>>(inp, out);
}